// round 6
// baseline (speedup 1.0000x reference)
#include <cuda_runtime.h>
#include <cuda_bf16.h>

#define TRUNC 2048
#define TLEN  2048
#define CAPV  200
#define NSM   148   // CTAs per channel = one full wave at 8 blocks/SM

// ---------------------------------------------------------------------------
// One-wave persistent kernel. Grid = (148, 8): blockIdx.y = channel,
// blockIdx.x = cta-within-channel. Each CTA:
//   1) builds its channel's 201-entry f(L) table in SMEM (cheap exp2-based pow)
//   2) stride-loops rows i = blockIdx.x + 148*r, filling each 2048-col row:
//        j > i                -> 0
//        d = i-j > far_thresh -> constant pattern (no table)
//        else                 -> table lookups (narrow diagonal band)
// ---------------------------------------------------------------------------
__global__ __launch_bounds__(256, 8)
void rem_kernel(const float* __restrict__ eta,
                const float* __restrict__ nu,
                const float* __restrict__ theta,
                float* __restrict__ out)
{
    __shared__ float tab[224];

    const int ch = blockIdx.y;
    const int cx = blockIdx.x;
    const int t  = threadIdx.x;
    const float4 zero4 = make_float4(0.f, 0.f, 0.f, 0.f);

    // ---- build table (201 entries) with cheap math ----
    if (t <= CAPV) {
        float fl = (float)t;
        float v;
        if (ch < 3) {
            // ipow(tanh(eta), L) = sgn * exp2(L * log2|lam|)
            float lam = tanhf(eta[ch]);
            if (t == 0) {
                v = 1.0f;
            } else {
                float lg = __log2f(fabsf(lam));
                v = exp2f(fl * lg);
                if ((t & 1) && lam < 0.0f) v = -v;
            }
        } else if (ch < 6) {
            int h = ch - 3;
            float x = nu[h];
            // sigmoid(x)^L = exp2(-L * log2(1 + e^-x))
            float lg = -__log2f(1.0f + __expf(-x));
            float mag = exp2f(fl * lg);
            float ang = theta[h] * fl;
            v = mag * ((h == 2) ? sinf(ang) : cosf(ang));
        } else {
            int h = ch - 3;          // 3, 4
            float ang = theta[h] * fl;
            v = (h == 3) ? cosf(ang) : sinf(ang);
        }
        tab[t] = v;
    }
    __syncthreads();

    int farth;                    // groups with jb < i - farth are "far"
    if      (ch == 2) farth = 806;
    else if (ch == 6) farth = 608;
    else              farth = 203;

    const float4* chbase =
        (const float4*)(out + (size_t)ch * TRUNC * TLEN);

    // stride loop over rows: i = cx, cx+148, ... (13-14 iterations)
    for (int i = cx; i < TRUNC; i += NSM) {
        float4* __restrict__ row4 =
            (float4*)chbase + (size_t)i * (TLEN / 4);

        // far-region pattern for this (ch, i): j-independent except ch6
        float4 farv;
        if (ch == 2) {
            int im = i & 3;
            farv.x = (im == 0) ? 1.f : 0.f;
            farv.y = (im == 1) ? 1.f : 0.f;
            farv.z = (im == 2) ? 1.f : 0.f;
            farv.w = (im == 3) ? 1.f : 0.f;
        } else if (ch == 5 || ch == 7) {
            farv = zero4;
        } else {
            farv = make_float4(1.f, 1.f, 1.f, 1.f);
        }

        #pragma unroll
        for (int g = 0; g < 2; g++) {
            int q  = t + (g << 8);
            int jb = q << 2;
            float4 rr;
            if (jb > i) {
                rr = zero4;
            } else if (jb < i - farth) {
                if (ch == 6) {
                    unsigned r3 = (unsigned)(i - jb) % 3u;
                    rr.x = (r3 == 0u) ? 1.f : 0.f;
                    rr.y = (r3 == 1u) ? 1.f : 0.f;
                    rr.z = (r3 == 2u) ? 1.f : 0.f;
                    rr.w = (r3 == 0u) ? 1.f : 0.f;
                } else {
                    rr = farv;
                }
            } else {
                // diagonal band: table lookups
                #pragma unroll
                for (int k = 0; k < 4; k++) {
                    int d = i - jb - k;
                    float v = 0.0f;
                    if (d >= 0) {
                        if (ch == 2) {
                            if ((d & 3) == 0) {
                                int dq = d >> 2;
                                v = tab[(dq > CAPV) ? 0 : dq];
                            }
                        } else if (ch == 6) {
                            unsigned ud = (unsigned)d;
                            if (ud % 3u == 0u) {
                                unsigned dq = ud / 3u;
                                v = tab[(dq > CAPV) ? 0 : (int)dq]
                                  * tab[(d  > CAPV) ? 0 : d];
                            }
                        } else if (ch == 7) {
                            if (d <= CAPV && (d & 1) == 0)
                                v = tab[d >> 1] * tab[d];
                        } else {
                            v = tab[(d > CAPV) ? 0 : d];
                        }
                        if (d == 0) v -= 1.0f;
                    }
                    ((float*)&rr)[k] = v;
                }
            }
            __stcs(&row4[q], rr);
        }
    }
}

extern "C" void kernel_launch(void* const* d_in, const int* in_sizes, int n_in,
                              void* d_out, int out_size)
{
    const float* eta   = (const float*)d_in[0];
    const float* nu    = (const float*)d_in[1];
    const float* theta = (const float*)d_in[2];
    float* out = (float*)d_out;

    rem_kernel<<<dim3(NSM, 8), 256>>>(eta, nu, theta, out);
}

// round 7
// speedup vs baseline: 1.0926x; 1.0926x over previous
#include <cuda_runtime.h>
#include <cuda_bf16.h>

#define TRUNC 2048
#define TLEN  2048
#define CAPV  200
#define RPB   2     // rows per block

// ---------------------------------------------------------------------------
// Fused single kernel, 256-bit stores (sm_100a st.global.v8.f32).
// One block = (RPB rows, 1 channel). 256 threads x 8 floats = one 2048-col row.
// Per block: build channel's 201-entry f(L) table in SMEM (cheap exp2 pow),
// then per row classify each thread's 8-float segment:
//   j0 > i                      -> all zero
//   all 8 elems beyond farth    -> constant pattern (no table)
//   else                        -> per-element table lookups (diagonal band)
// ---------------------------------------------------------------------------
__global__ __launch_bounds__(256)
void rem_kernel(const float* __restrict__ eta,
                const float* __restrict__ nu,
                const float* __restrict__ theta,
                float* __restrict__ out)
{
    __shared__ float tab[224];

    const int ch = blockIdx.y;
    const int i0 = blockIdx.x * RPB;
    const int t  = threadIdx.x;

    // ---- build table (201 entries) with cheap math ----
    if (t <= CAPV) {
        float fl = (float)t;
        float v;
        if (ch < 3) {
            float lam = tanhf(eta[ch]);
            if (t == 0) {
                v = 1.0f;
            } else {
                float lg = __log2f(fabsf(lam));
                v = exp2f(fl * lg);
                if ((t & 1) && lam < 0.0f) v = -v;
            }
        } else if (ch < 6) {
            int h = ch - 3;
            float x = nu[h];
            float lg = -__log2f(1.0f + __expf(-x));   // log2(sigmoid)
            float mag = exp2f(fl * lg);
            float ang = theta[h] * fl;
            v = mag * ((h == 2) ? sinf(ang) : cosf(ang));
        } else {
            int h = ch - 3;          // 3, 4
            float ang = theta[h] * fl;
            v = (h == 3) ? cosf(ang) : sinf(ang);
        }
        tab[t] = v;
    }
    __syncthreads();

    int farth;                    // d > farth guaranteed "far" for all 8 elems
    if      (ch == 2) farth = 806;
    else if (ch == 6) farth = 608;
    else              farth = 203;

    const int j0 = t << 3;        // this thread's 8-float segment start

    #pragma unroll
    for (int r = 0; r < RPB; r++) {
        const int i = i0 + r;
        float* __restrict__ rowp =
            out + ((size_t)ch * TRUNC + (size_t)i) * TLEN + j0;

        float v[8];
        if (j0 > i) {
            #pragma unroll
            for (int k = 0; k < 8; k++) v[k] = 0.0f;
        } else if (j0 + farth + 7 < i) {
            // far region: constants only
            if (ch == 2) {
                int im = i & 3;                    // j0 % 4 == 0
                #pragma unroll
                for (int k = 0; k < 8; k++) v[k] = ((k & 3) == im) ? 1.f : 0.f;
            } else if (ch == 6) {
                int r3 = (i - j0) % 3;             // d = r3 - k (mod 3)
                #pragma unroll
                for (int k = 0; k < 8; k++) v[k] = ((k % 3) == r3) ? 1.f : 0.f;
            } else if (ch == 5 || ch == 7) {
                #pragma unroll
                for (int k = 0; k < 8; k++) v[k] = 0.0f;
            } else {
                #pragma unroll
                for (int k = 0; k < 8; k++) v[k] = 1.0f;
            }
        } else {
            // diagonal band: general table-lookup path (covers all d >= 0)
            #pragma unroll
            for (int k = 0; k < 8; k++) {
                int d = i - j0 - k;
                float x = 0.0f;
                if (d >= 0) {
                    if (ch == 2) {
                        if ((d & 3) == 0) {
                            int dq = d >> 2;
                            x = tab[(dq > CAPV) ? 0 : dq];
                        }
                    } else if (ch == 6) {
                        unsigned ud = (unsigned)d;
                        if (ud % 3u == 0u) {
                            unsigned dq = ud / 3u;
                            x = tab[(dq > CAPV) ? 0 : (int)dq]
                              * tab[(d  > CAPV) ? 0 : d];
                        }
                    } else if (ch == 7) {
                        if (d <= CAPV && (d & 1) == 0)
                            x = tab[d >> 1] * tab[d];
                    } else {
                        x = tab[(d > CAPV) ? 0 : d];
                    }
                    if (d == 0) x -= 1.0f;
                }
                v[k] = x;
            }
        }

        // 256-bit streaming store (Blackwell)
        asm volatile(
            "st.global.cs.v8.f32 [%0], {%1, %2, %3, %4, %5, %6, %7, %8};"
            :: "l"(rowp),
               "f"(v[0]), "f"(v[1]), "f"(v[2]), "f"(v[3]),
               "f"(v[4]), "f"(v[5]), "f"(v[6]), "f"(v[7])
            : "memory");
    }
}

extern "C" void kernel_launch(void* const* d_in, const int* in_sizes, int n_in,
                              void* d_out, int out_size)
{
    const float* eta   = (const float*)d_in[0];
    const float* nu    = (const float*)d_in[1];
    const float* theta = (const float*)d_in[2];
    float* out = (float*)d_out;

    rem_kernel<<<dim3(TRUNC / RPB, 8), 256>>>(eta, nu, theta, out);
}

// round 10
// speedup vs baseline: 1.1227x; 1.0275x over previous
#include <cuda_runtime.h>
#include <cuda_bf16.h>

#define TRUNC 2048
#define TLEN  2048
#define CAPV  200

// ---------------------------------------------------------------------------
// Fused single kernel. One block = (1 row, 1 channel), grid (2048, 8).
// Per block: build channel's 201-entry f(L) table in SMEM (cheap exp2 pow),
// then region-structured fill of the 2048-col row with default writeback
// stores (output ~ L2-sized; graph replays re-dirty resident lines, so the
// L2/LTS path, not the DRAM write stream, should bind).
//   j > i                 -> 0
//   d = i-j > far_thresh  -> constant pattern (no table)
//   else                  -> table lookups (narrow diagonal band)
// ---------------------------------------------------------------------------
__global__ __launch_bounds__(256)
void rem_kernel(const float* __restrict__ eta,
                const float* __restrict__ nu,
                const float* __restrict__ theta,
                float* __restrict__ out)
{
    __shared__ float tab[224];

    const int ch = blockIdx.y;
    const int i  = blockIdx.x;
    const int t  = threadIdx.x;
    const float4 zero4 = make_float4(0.f, 0.f, 0.f, 0.f);

    // ---- build table (201 entries) with cheap math ----
    if (t <= CAPV) {
        float fl = (float)t;
        float v;
        if (ch < 3) {
            float lam = tanhf(eta[ch]);
            if (t == 0) {
                v = 1.0f;
            } else {
                float lg = __log2f(fabsf(lam));
                v = exp2f(fl * lg);
                if ((t & 1) && lam < 0.0f) v = -v;
            }
        } else if (ch < 6) {
            int h = ch - 3;
            float x = nu[h];
            float lg = -__log2f(1.0f + __expf(-x));   // log2(sigmoid)
            float mag = exp2f(fl * lg);
            float ang = theta[h] * fl;
            v = mag * ((h == 2) ? sinf(ang) : cosf(ang));
        } else {
            int h = ch - 3;          // 3, 4
            float ang = theta[h] * fl;
            v = (h == 3) ? cosf(ang) : sinf(ang);
        }
        tab[t] = v;
    }
    __syncthreads();

    int farth;                    // groups with jb < i - farth are "far"
    if      (ch == 2) farth = 806;
    else if (ch == 6) farth = 608;
    else              farth = 203;

    float4* __restrict__ row4 =
        (float4*)(out + ((size_t)ch * TRUNC + (size_t)i) * TLEN);

    // far-region pattern for this (ch, i): j-independent except ch6
    float4 farv;
    if (ch == 2) {
        int im = i & 3;
        farv.x = (im == 0) ? 1.f : 0.f;
        farv.y = (im == 1) ? 1.f : 0.f;
        farv.z = (im == 2) ? 1.f : 0.f;
        farv.w = (im == 3) ? 1.f : 0.f;
    } else if (ch == 5 || ch == 7) {
        farv = zero4;
    } else {
        farv = make_float4(1.f, 1.f, 1.f, 1.f);
    }

    #pragma unroll
    for (int g = 0; g < 2; g++) {
        int q  = t + (g << 8);
        int jb = q << 2;
        float4 rr;
        if (jb > i) {
            rr = zero4;
        } else if (jb < i - farth) {
            if (ch == 6) {
                unsigned r3 = (unsigned)(i - jb) % 3u;
                rr.x = (r3 == 0u) ? 1.f : 0.f;
                rr.y = (r3 == 1u) ? 1.f : 0.f;
                rr.z = (r3 == 2u) ? 1.f : 0.f;
                rr.w = (r3 == 0u) ? 1.f : 0.f;
            } else {
                rr = farv;
            }
        } else {
            // diagonal band: table lookups (general path, covers all d >= 0)
            #pragma unroll
            for (int k = 0; k < 4; k++) {
                int d = i - jb - k;
                float v = 0.0f;
                if (d >= 0) {
                    if (ch == 2) {
                        if ((d & 3) == 0) {
                            int dq = d >> 2;
                            v = tab[(dq > CAPV) ? 0 : dq];
                        }
                    } else if (ch == 6) {
                        unsigned ud = (unsigned)d;
                        if (ud % 3u == 0u) {
                            unsigned dq = ud / 3u;
                            v = tab[(dq > CAPV) ? 0 : (int)dq]
                              * tab[(d  > CAPV) ? 0 : d];
                        }
                    } else if (ch == 7) {
                        if (d <= CAPV && (d & 1) == 0)
                            v = tab[d >> 1] * tab[d];
                    } else {
                        v = tab[(d > CAPV) ? 0 : d];
                    }
                    if (d == 0) v -= 1.0f;
                }
                ((float*)&rr)[k] = v;
            }
        }
        row4[q] = rr;   // default writeback store
    }
}

extern "C" void kernel_launch(void* const* d_in, const int* in_sizes, int n_in,
                              void* d_out, int out_size)
{
    const float* eta   = (const float*)d_in[0];
    const float* nu    = (const float*)d_in[1];
    const float* theta = (const float*)d_in[2];
    float* out = (float*)d_out;

    rem_kernel<<<dim3(TRUNC, 8), 256>>>(eta, nu, theta, out);
}

// round 11
// speedup vs baseline: 1.1680x; 1.0404x over previous
#include <cuda_runtime.h>
#include <cuda_bf16.h>

#define TRUNC 2048
#define TLEN  2048
#define CAPV  200
#define RPB   2     // rows per block

// ---------------------------------------------------------------------------
// Fused single kernel. One block = (2 rows, 1 channel), grid (1024, 8).
// Store path is at the chip LTS cap (~6.2 TB/s); all that matters beyond the
// fill structure is minimizing per-block overhead:
//  - table build uses only MUFU-class math (__expf, __sinf, __cosf, exp2f)
//  - RPB=2 balances table amortization (8192 builds) vs wave tail (6.9 waves)
// Fill regions per row i (d = i-j):
//   j > i                 -> 0
//   d > far_thresh        -> constant pattern (no table)
//   else                  -> table lookups (narrow diagonal band)
// ---------------------------------------------------------------------------
__global__ __launch_bounds__(256)
void rem_kernel(const float* __restrict__ eta,
                const float* __restrict__ nu,
                const float* __restrict__ theta,
                float* __restrict__ out)
{
    __shared__ float tab[224];

    const int ch = blockIdx.y;
    const int i0 = blockIdx.x * RPB;
    const int t  = threadIdx.x;
    const float4 zero4 = make_float4(0.f, 0.f, 0.f, 0.f);

    // ---- build table (201 entries), MUFU-only math ----
    if (t <= CAPV) {
        float fl = (float)t;
        float v;
        if (ch < 3) {
            // tanh(x) = 1 - 2/(e^{2x}+1)  (MUFU exp + rcp)
            float x   = eta[ch];
            float lam = 1.0f - 2.0f * __frcp_rn(__expf(2.0f * x) + 1.0f);
            if (t == 0) {
                v = 1.0f;
            } else {
                v = exp2f(fl * __log2f(fabsf(lam)));
                if ((t & 1) && lam < 0.0f) v = -v;
            }
        } else if (ch < 6) {
            int h = ch - 3;
            float x  = nu[h];
            // sigmoid(x)^L = exp2(-L * log2(1 + e^-x))
            float lg  = -__log2f(1.0f + __expf(-x));
            float mag = exp2f(fl * lg);
            float ang = theta[h] * fl;
            v = mag * ((h == 2) ? __sinf(ang) : __cosf(ang));
        } else {
            int h = ch - 3;          // 3, 4
            float ang = theta[h] * fl;
            v = (h == 3) ? __cosf(ang) : __sinf(ang);
        }
        tab[t] = v;
    }
    __syncthreads();

    int farth;                    // groups with jb < i - farth are "far"
    if      (ch == 2) farth = 806;
    else if (ch == 6) farth = 608;
    else              farth = 203;

    #pragma unroll
    for (int r = 0; r < RPB; r++) {
        const int i = i0 + r;
        float4* __restrict__ row4 =
            (float4*)(out + ((size_t)ch * TRUNC + (size_t)i) * TLEN);

        // far-region pattern for this (ch, i): j-independent except ch6
        float4 farv;
        if (ch == 2) {
            int im = i & 3;
            farv.x = (im == 0) ? 1.f : 0.f;
            farv.y = (im == 1) ? 1.f : 0.f;
            farv.z = (im == 2) ? 1.f : 0.f;
            farv.w = (im == 3) ? 1.f : 0.f;
        } else if (ch == 5 || ch == 7) {
            farv = zero4;
        } else {
            farv = make_float4(1.f, 1.f, 1.f, 1.f);
        }

        #pragma unroll
        for (int g = 0; g < 2; g++) {
            int q  = t + (g << 8);
            int jb = q << 2;
            float4 rr;
            if (jb > i) {
                rr = zero4;
            } else if (jb < i - farth) {
                if (ch == 6) {
                    unsigned r3 = (unsigned)(i - jb) % 3u;
                    rr.x = (r3 == 0u) ? 1.f : 0.f;
                    rr.y = (r3 == 1u) ? 1.f : 0.f;
                    rr.z = (r3 == 2u) ? 1.f : 0.f;
                    rr.w = (r3 == 0u) ? 1.f : 0.f;
                } else {
                    rr = farv;
                }
            } else {
                // diagonal band: table lookups (general path, covers all d >= 0)
                #pragma unroll
                for (int k = 0; k < 4; k++) {
                    int d = i - jb - k;
                    float v = 0.0f;
                    if (d >= 0) {
                        if (ch == 2) {
                            if ((d & 3) == 0) {
                                int dq = d >> 2;
                                v = tab[(dq > CAPV) ? 0 : dq];
                            }
                        } else if (ch == 6) {
                            unsigned ud = (unsigned)d;
                            if (ud % 3u == 0u) {
                                unsigned dq = ud / 3u;
                                v = tab[(dq > CAPV) ? 0 : (int)dq]
                                  * tab[(d  > CAPV) ? 0 : d];
                            }
                        } else if (ch == 7) {
                            if (d <= CAPV && (d & 1) == 0)
                                v = tab[d >> 1] * tab[d];
                        } else {
                            v = tab[(d > CAPV) ? 0 : d];
                        }
                        if (d == 0) v -= 1.0f;
                    }
                    ((float*)&rr)[k] = v;
                }
            }
            row4[q] = rr;
        }
    }
}

extern "C" void kernel_launch(void* const* d_in, const int* in_sizes, int n_in,
                              void* d_out, int out_size)
{
    const float* eta   = (const float*)d_in[0];
    const float* nu    = (const float*)d_in[1];
    const float* theta = (const float*)d_in[2];
    float* out = (float*)d_out;

    rem_kernel<<<dim3(TRUNC / RPB, 8), 256>>>(eta, nu, theta, out);
}